// round 15
// baseline (speedup 1.0000x reference)
#include <cuda_runtime.h>
#include <math.h>
#include <stdint.h>

#define B_   4
#define S_   2048
#define H_   16
#define DH   64
#define DM   1024
#define MTOT (B_*S_)   // 8192
#define QKVOFF ((size_t)B_*H_*S_*DH)
#define QSCALE 0.180336880111120419f   // 0.125 * log2(e)

// perm3: within each 8-group, logical index c stored at position (c&3)*2+(c>>2)
// i.e. order [0,4,1,5,2,6,3,7]; positions 2g, 2g+1 hold logical g, g+4.
#define PERM3(c) ((((c) & 3) << 1) | ((c) >> 2))

// -------------------------- device scratch (no allocs) ---------------------
__device__ float g_qkv[3 * QKVOFF];          // Q(prescaled)/K(d-permuted)/V, tf32
__device__ float g_o[(size_t)B_*S_*DM];      // tf32 attention out
__device__ float g_xt[(size_t)MTOT*DM];      // tf32 x, k-columns permuted
__device__ float g_wqkv[3 * DM * DM];        // tf32 WQ|WK|WV (natural layout)
__device__ float g_wot[DM * DM];             // tf32 WO
__device__ float g_bias[3 * DM];             // bQ|bK|bV

// -------------------------- PTX helpers ------------------------------------
__device__ __forceinline__ uint32_t f2tf(float x) {
    uint32_t r;
    asm("cvt.rna.tf32.f32 %0, %1;" : "=r"(r) : "f"(x));
    return r;
}
__device__ __forceinline__ float ex2(float x) {
    float r;
    asm("ex2.approx.f32 %0, %1;" : "=f"(r) : "f"(x));
    return r;
}
__device__ __forceinline__ void mma_tf32(float c[4], const uint32_t a[4],
                                         const uint32_t b[2]) {
    asm volatile(
        "mma.sync.aligned.m16n8k8.row.col.f32.tf32.tf32.f32 "
        "{%0,%1,%2,%3}, {%4,%5,%6,%7}, {%8,%9}, {%0,%1,%2,%3};"
        : "+f"(c[0]), "+f"(c[1]), "+f"(c[2]), "+f"(c[3])
        : "r"(a[0]), "r"(a[1]), "r"(a[2]), "r"(a[3]), "r"(b[0]), "r"(b[1]));
}
__device__ __forceinline__ uint32_t smem_u32(const void* p) {
    uint32_t a;
    asm("{ .reg .u64 t; cvta.to.shared.u64 t, %1; cvt.u32.u64 %0, t; }"
        : "=r"(a) : "l"(p));
    return a;
}
__device__ __forceinline__ void cp16(uint32_t dst, const void* src) {
    asm volatile("cp.async.cg.shared.global [%0], [%1], 16;"
                 :: "r"(dst), "l"(src));
}
#define CP_COMMIT() asm volatile("cp.async.commit_group;" ::: "memory")
#define CP_WAIT0()  asm volatile("cp.async.wait_group 0;" ::: "memory")

// ---------------- tf32 pre-round: x (k-columns permuted) --------------------
__global__ void preround_x(const float* __restrict__ in, float* __restrict__ out,
                           int n4)
{
    int i = blockIdx.x * blockDim.x + threadIdx.x;
    if (i < n4) {
        float4 v = ((const float4*)in)[i];
        int idx  = i * 4;                 // element index; d = idx & 1023
        int base = idx & ~7;              // 8-group start (flat; rows are 1024-mult)
        int off  = (idx & 4) ? 1 : 0;     // locals {0..3}->pos{0,2,4,6}; {4..7}->{1,3,5,7}
        out[base + off + 0] = __uint_as_float(f2tf(v.x));
        out[base + off + 2] = __uint_as_float(f2tf(v.y));
        out[base + off + 4] = __uint_as_float(f2tf(v.z));
        out[base + off + 6] = __uint_as_float(f2tf(v.w));
    }
}

__global__ void preround_w(const float* __restrict__ WQ, const float* __restrict__ WK,
                           const float* __restrict__ WV, const float* __restrict__ WO,
                           float* __restrict__ wqkv, float* __restrict__ wo)
{
    const int z = blockIdx.y;
    const float* in = (z == 0) ? WQ : (z == 1) ? WK : (z == 2) ? WV : WO;
    float* out = (z < 3) ? wqkv + (size_t)z * DM * DM : wo;
    int i = blockIdx.x * blockDim.x + threadIdx.x;
    float4 v = ((const float4*)in)[i];
    float4 o;
    o.x = __uint_as_float(f2tf(v.x)); o.y = __uint_as_float(f2tf(v.y));
    o.z = __uint_as_float(f2tf(v.z)); o.w = __uint_as_float(f2tf(v.w));
    ((float4*)out)[i] = o;
}

// ---------------------------------------------------------------------------
// Tensor-core tf32 GEMM, warp tile 64x64.
// WMODE 0: fused QKV, persistent grid, A = g_xt (k-permuted -> paired af LDS.64),
//          K output d-permuted, Q prescaled.
// WMODE 1: O-proj, one tile per block, scalar af (A = g_o natural).
// ---------------------------------------------------------------------------
#define PAD_W 136
#define WSZ (32 * PAD_W)
#define NKT (DM / 32)

template<int WMODE>
__device__ __forceinline__ void stage_async(
    const float* __restrict__ A, const float* __restrict__ W,
    uint32_t as, uint32_t ws, int m0, int n0, int k0, int tid, int pad_a)
{
#pragma unroll
    for (int i = 0; i < 8; i++) {
        int idx = tid + i * 128;
        int r   = idx >> 3;
        int c4  = (idx & 7) << 2;
        cp16(as + (r * pad_a + c4) * 4, A + (size_t)(m0 + r) * DM + k0 + c4);
    }
#pragma unroll
    for (int i = 0; i < 8; i++) {
        int idx = tid + i * 128;
        int r   = idx >> 5;
        int c4  = (idx & 31) << 2;
        const float* wp;
        if (WMODE == 0) {
            int n = n0 + c4;
            int sel = n >> 10, nn = n & 1023;
            int h = nn >> 6, e = nn & 63;
            wp = W + (size_t)sel * DM * DM + ((size_t)h * DM + (k0 + r)) * 64 + e;
        } else {
            wp = W + (size_t)(k0 + r) * DM + n0 + c4;
        }
        cp16(ws + (r * PAD_W + c4) * 4, wp);
    }
}

template<int WMODE>
__global__ void __launch_bounds__(128, 2)
gemm_mma(const float* __restrict__ A, const float* __restrict__ W,
         const float* __restrict__ bias, float* __restrict__ out)
{
    constexpr int PA  = (WMODE == 0) ? 40 : 36;   // paired LDS.64 needs 8gr bank walk
    constexpr int ASZ = 128 * PA;
    constexpr int NTW = (WMODE == 0) ? 24 : 8;    // n-tiles per tile-row
    constexpr int TOT = (WMODE == 0) ? 1536 : 512;

    extern __shared__ float sm[];
    float* As = sm;
    float* Ws = sm + 2 * ASZ;
    const uint32_t asu = smem_u32(As);
    const uint32_t wsu = smem_u32(Ws);

    const int tid  = threadIdx.x;
    const int lane = tid & 31;
    const int wid  = tid >> 5;
    const int mw   = (wid & 1) * 64;
    const int nw   = (wid >> 1) * 64;
    const int gr   = lane >> 2;
    const int gc   = lane & 3;

    int t  = blockIdx.x;
    int m0 = (t / NTW) * 128;
    int n0 = (t % NTW) * 128;

    stage_async<WMODE>(A, W, asu, wsu, m0, n0, 0, tid, PA);
    CP_COMMIT();

    while (true) {
        const int  tn       = t + gridDim.x;
        const bool has_next = (WMODE == 0) && (tn < TOT);
        const int  nm0      = has_next ? (tn / NTW) * 128 : 0;
        const int  nn0      = has_next ? (tn % NTW) * 128 : 0;

        float c[4][8][4];
#pragma unroll
        for (int mt = 0; mt < 4; mt++)
#pragma unroll
            for (int nt = 0; nt < 8; nt++)
#pragma unroll
                for (int j = 0; j < 4; j++) c[mt][nt][j] = 0.f;

        for (int i = 0; i < NKT; i++) {
            const int p = i & 1;
            CP_WAIT0();
            __syncthreads();
            if (i + 1 < NKT) {
                stage_async<WMODE>(A, W, asu + ((p ^ 1) * ASZ) * 4,
                                   wsu + ((p ^ 1) * WSZ) * 4,
                                   m0, n0, (i + 1) * 32, tid, PA);
                CP_COMMIT();
            } else if (has_next) {
                stage_async<WMODE>(A, W, asu + ((p ^ 1) * ASZ) * 4,
                                   wsu + ((p ^ 1) * WSZ) * 4,
                                   nm0, nn0, 0, tid, PA);
                CP_COMMIT();
            }

            const float* as = As + p * ASZ + mw * PA;
            const float* ws = Ws + p * WSZ + nw;
#pragma unroll
            for (int ks = 0; ks < 32; ks += 8) {
                uint32_t af[4][4];
#pragma unroll
                for (int mt = 0; mt < 4; mt++) {
                    if (WMODE == 0) {
                        // A k-columns permuted: pos 2gc,2gc+1 = logical gc,gc+4
                        const float* ap = as + (mt * 16 + gr) * PA + ks + 2 * gc;
                        float2 a0 = *(const float2*)ap;
                        float2 a1 = *(const float2*)(ap + 8 * PA);
                        af[mt][0] = __float_as_uint(a0.x);
                        af[mt][2] = __float_as_uint(a0.y);
                        af[mt][1] = __float_as_uint(a1.x);
                        af[mt][3] = __float_as_uint(a1.y);
                    } else {
                        const float* ap = as + (mt * 16 + gr) * PA + ks + gc;
                        af[mt][0] = __float_as_uint(ap[0]);
                        af[mt][1] = __float_as_uint(ap[8 * PA]);
                        af[mt][2] = __float_as_uint(ap[4]);
                        af[mt][3] = __float_as_uint(ap[8 * PA + 4]);
                    }
                }
                uint32_t bf[8][2];
#pragma unroll
                for (int nt = 0; nt < 8; nt++) {
                    const float* bp = ws + (ks + gc) * PAD_W + nt * 8 + gr;
                    bf[nt][0] = __float_as_uint(bp[0]);
                    bf[nt][1] = __float_as_uint(bp[4 * PAD_W]);
                }
#pragma unroll
                for (int mt = 0; mt < 4; mt++)
#pragma unroll
                    for (int nt = 0; nt < 8; nt++)
                        mma_tf32(c[mt][nt], af[mt], bf[nt]);
            }
        }

        // ---- epilogue for tile (m0, n0) ----
        const int sel   = (WMODE == 0) ? (n0 >> 10) : 0;
        const float scl = (WMODE == 0 && sel == 0) ? QSCALE : 1.0f;
        float* outb = (WMODE == 0) ? out + (size_t)sel * QKVOFF : out;

#pragma unroll
        for (int mt = 0; mt < 4; mt++) {
#pragma unroll
            for (int half = 0; half < 2; half++) {
                int m = m0 + mw + mt * 16 + gr + half * 8;
                int bb = m >> 11, ss = m & (S_ - 1);
#pragma unroll
                for (int nt = 0; nt < 8; nt++) {
                    int n = n0 + nw + nt * 8 + 2 * gc;
                    float2 val;
                    val.x = c[mt][nt][half * 2 + 0] + bias[n];
                    val.y = c[mt][nt][half * 2 + 1] + bias[n + 1];
                    if (WMODE == 0) {
                        val.x = __uint_as_float(f2tf(val.x * scl));
                        val.y = __uint_as_float(f2tf(val.y * scl));
                        int nn = n & 1023;
                        int h = nn >> 6, e = nn & 63;
                        float* ob = outb + (((size_t)bb * H_ + h) * S_ + ss) * DH;
                        if (sel == 1) {
                            // K: store d-permuted (per 8-group)
                            int e0 = (e & ~7) | PERM3(e & 7);
                            int e1 = (e & ~7) | PERM3((e + 1) & 7);
                            ob[e0] = val.x;
                            ob[e1] = val.y;
                        } else {
                            *(float2*)(ob + e) = val;
                        }
                    } else {
                        *(float2*)(outb + (size_t)m * DM + n) = val;
                    }
                }
            }
        }

        if (!has_next) break;
        t = tn; m0 = nm0; n0 = nn0;
    }
}

#define GSMEM0 (2 * (128 * 40 + WSZ) * 4)   // 75776
#define GSMEM1 (2 * (128 * 36 + WSZ) * 4)   // 71680

// ---------------------------------------------------------------------------
// Tensor-core tf32 flash attention (R12 structure), K d-permuted so the
// B-fragment is one LDS.64; Ks row stride 72 keeps it conflict-free.
// ---------------------------------------------------------------------------
#define AST 68
#define KST 72
#define KSZ (64 * KST)
#define VSZ (64 * AST)
#define ATT_SMEM ((128*AST + 2*KSZ + 2*VSZ) * 4)   // 106496

__global__ void __launch_bounds__(128, 2)
attn_mma(const float* __restrict__ Q, const float* __restrict__ K,
         const float* __restrict__ V, float* __restrict__ O)
{
    extern __shared__ float sm[];
    float* Pt = sm;
    float* Ks = sm + 128 * AST;      // [2][64][KST]
    float* Vs = Ks + 2 * KSZ;        // [2][64][AST]
    const uint32_t ksu = smem_u32(Ks);
    const uint32_t vsu = smem_u32(Vs);

    const int tid  = threadIdx.x;
    const int lane = tid & 31;
    const int wid  = tid >> 5;
    const int mw   = wid * 32;
    const int gr   = lane >> 2;
    const int gc   = lane & 3;
    const int bh   = blockIdx.y;
    const int q0   = blockIdx.x * 128;

    const float* Qp = Q + ((size_t)bh * S_ + q0) * DH;
    const float* Kp = K + (size_t)bh * S_ * DH;
    const float* Vp = V + (size_t)bh * S_ * DH;

    // prefetch K/V tile 0
#pragma unroll
    for (int i = 0; i < 8; i++) {
        int idx = tid + i * 128;
        int r   = idx >> 4;
        int c4  = (idx & 15) << 2;
        cp16(ksu + (r * KST + c4) * 4, Kp + (size_t)r * DH + c4);
        cp16(vsu + (r * AST + c4) * 4, Vp + (size_t)r * DH + c4);
    }
    CP_COMMIT();

    uint32_t aq[2][8][4];
#pragma unroll
    for (int mt = 0; mt < 2; mt++) {
        const float* qr0 = Qp + (mw + mt * 16 + gr) * DH;
#pragma unroll
        for (int ks = 0; ks < 8; ks++) {
            aq[mt][ks][0] = __float_as_uint(qr0[ks * 8 + gc]);
            aq[mt][ks][1] = __float_as_uint(qr0[8 * DH + ks * 8 + gc]);
            aq[mt][ks][2] = __float_as_uint(qr0[ks * 8 + gc + 4]);
            aq[mt][ks][3] = __float_as_uint(qr0[8 * DH + ks * 8 + gc + 4]);
        }
    }

    float lpart[2][2] = {{0.f, 0.f}, {0.f, 0.f}};
    float co[2][8][4];
#pragma unroll
    for (int mt = 0; mt < 2; mt++)
#pragma unroll
        for (int nt = 0; nt < 8; nt++)
#pragma unroll
            for (int j = 0; j < 4; j++) co[mt][nt][j] = 0.f;

    const int NT = S_ / 64;
    for (int it = 0; it < NT; it++) {
        const int p = it & 1;
        CP_WAIT0();
        __syncthreads();
        if (it + 1 < NT) {
            const int kt1 = (it + 1) * 64;
#pragma unroll
            for (int i = 0; i < 8; i++) {
                int idx = tid + i * 128;
                int r   = idx >> 4;
                int c4  = (idx & 15) << 2;
                cp16(ksu + ((p ^ 1) * KSZ + r * KST + c4) * 4,
                     Kp + (size_t)(kt1 + r) * DH + c4);
                cp16(vsu + ((p ^ 1) * VSZ + r * AST + c4) * 4,
                     Vp + (size_t)(kt1 + r) * DH + c4);
            }
            CP_COMMIT();
        }

        const float* ksb = Ks + p * KSZ;
        const float* vsb = Vs + p * VSZ;

        // ---- S = Q @ K^T (log2-domain); K d-permuted -> paired LDS.64 ----
        float s[2][8][4];
#pragma unroll
        for (int mt = 0; mt < 2; mt++)
#pragma unroll
            for (int nt = 0; nt < 8; nt++)
#pragma unroll
                for (int j = 0; j < 4; j++) s[mt][nt][j] = 0.f;

#pragma unroll
        for (int ks = 0; ks < 8; ks++) {
            uint32_t bk[8][2];
#pragma unroll
            for (int nt = 0; nt < 8; nt++) {
                float2 b2 = *(const float2*)(ksb + (nt * 8 + gr) * KST
                                             + ks * 8 + 2 * gc);
                bk[nt][0] = __float_as_uint(b2.x);   // logical d = ks*8+gc
                bk[nt][1] = __float_as_uint(b2.y);   // logical d = ks*8+gc+4
            }
#pragma unroll
            for (int mt = 0; mt < 2; mt++)
#pragma unroll
                for (int nt = 0; nt < 8; nt++)
                    mma_tf32(s[mt][nt], aq[mt][ks], bk[nt]);
        }

        // ---- max-free softmax + P stash ----
#pragma unroll
        for (int mt = 0; mt < 2; mt++) {
#pragma unroll
            for (int hf = 0; hf < 2; hf++) {
                float* pp = Pt + (mw + mt * 16 + gr + 8 * hf) * AST;
                float psum = 0.f;
#pragma unroll
                for (int nt = 0; nt < 8; nt++) {
                    float p0 = ex2(s[mt][nt][hf * 2]);
                    float p1 = ex2(s[mt][nt][hf * 2 + 1]);
                    psum += p0 + p1;
                    float2 pv;
                    pv.x = __uint_as_float(f2tf(p0));
                    pv.y = __uint_as_float(f2tf(p1));
                    *(float2*)(pp + nt * 8 + 2 * gc) = pv;
                }
                lpart[mt][hf] += psum;
            }
        }
        __syncwarp();

        // ---- O += P @ V ----
#pragma unroll
        for (int ks = 0; ks < 8; ks++) {
            uint32_t ap[2][4];
#pragma unroll
            for (int mt = 0; mt < 2; mt++) {
                const float* pp = Pt + (mw + mt * 16 + gr) * AST + ks * 8 + gc;
                ap[mt][0] = __float_as_uint(pp[0]);
                ap[mt][1] = __float_as_uint(pp[8 * AST]);
                ap[mt][2] = __float_as_uint(pp[4]);
                ap[mt][3] = __float_as_uint(pp[8 * AST + 4]);
            }
            uint32_t bv[8][2];
#pragma unroll
            for (int nt = 0; nt < 8; nt++) {
                const float* vp = vsb + (ks * 8 + gc) * AST + nt * 8 + gr;
                bv[nt][0] = __float_as_uint(vp[0]);
                bv[nt][1] = __float_as_uint(vp[4 * AST]);
            }
#pragma unroll
            for (int mt = 0; mt < 2; mt++)
#pragma unroll
                for (int nt = 0; nt < 8; nt++)
                    mma_tf32(co[mt][nt], ap[mt], bv[nt]);
        }
    }

    // ---- epilogue ----
    const int b = bh >> 4, h = bh & 15;
#pragma unroll
    for (int mt = 0; mt < 2; mt++) {
#pragma unroll
        for (int hf = 0; hf < 2; hf++) {
            float l = lpart[mt][hf];
            l += __shfl_xor_sync(0xffffffffu, l, 1);
            l += __shfl_xor_sync(0xffffffffu, l, 2);
            float inv = 1.f / l;
            int q = q0 + mw + mt * 16 + gr + 8 * hf;
            float* op = O + ((size_t)b * S_ + q) * DM + h * DH;
#pragma unroll
            for (int nt = 0; nt < 8; nt++) {
                float2 val;
                val.x = __uint_as_float(f2tf(co[mt][nt][hf * 2]     * inv));
                val.y = __uint_as_float(f2tf(co[mt][nt][hf * 2 + 1] * inv));
                *(float2*)(op + nt * 8 + 2 * gc) = val;
            }
        }
    }
}

// ---------------------------------------------------------------------------
extern "C" void kernel_launch(void* const* d_in, const int* in_sizes, int n_in,
                              void* d_out, int out_size)
{
    (void)in_sizes; (void)n_in; (void)out_size;
    const float* x  = (const float*)d_in[0];
    const float* WQ = (const float*)d_in[1];
    const float* WK = (const float*)d_in[2];
    const float* WV = (const float*)d_in[3];
    const float* WO = (const float*)d_in[4];
    const float* bQ = (const float*)d_in[5];
    const float* bK = (const float*)d_in[6];
    const float* bV = (const float*)d_in[7];
    const float* bO = (const float*)d_in[8];
    float* out = (float*)d_out;

    void *pqkv, *po, *pxt, *pwqkv, *pwo, *pbias;
    cudaGetSymbolAddress(&pqkv, g_qkv);
    cudaGetSymbolAddress(&po, g_o);
    cudaGetSymbolAddress(&pxt, g_xt);
    cudaGetSymbolAddress(&pwqkv, g_wqkv);
    cudaGetSymbolAddress(&pwo, g_wot);
    cudaGetSymbolAddress(&pbias, g_bias);

    static int attr_set = 0;
    if (!attr_set) {
        cudaFuncSetAttribute(attn_mma, cudaFuncAttributeMaxDynamicSharedMemorySize,
                             ATT_SMEM);
        cudaFuncSetAttribute(gemm_mma<0>, cudaFuncAttributeMaxDynamicSharedMemorySize,
                             GSMEM0);
        cudaFuncSetAttribute(gemm_mma<1>, cudaFuncAttributeMaxDynamicSharedMemorySize,
                             GSMEM1);
        attr_set = 1;
    }

    preround_x<<<(MTOT * DM / 4 + 255) / 256, 256>>>(x, (float*)pxt, MTOT * DM / 4);
    preround_w<<<dim3(DM * DM / 4 / 256, 4), 256>>>(WQ, WK, WV, WO,
                                                    (float*)pwqkv, (float*)pwo);
    cudaMemcpyAsync((float*)pbias,          bQ, DM * 4, cudaMemcpyDeviceToDevice);
    cudaMemcpyAsync((float*)pbias + DM,     bK, DM * 4, cudaMemcpyDeviceToDevice);
    cudaMemcpyAsync((float*)pbias + 2 * DM, bV, DM * 4, cudaMemcpyDeviceToDevice);

    // Fused QKV projection: persistent grid over 1536 tiles
    gemm_mma<0><<<304, 128, GSMEM0>>>((const float*)pxt, (const float*)pwqkv,
                                      (const float*)pbias, (float*)pqkv);

    const float* Qb = (const float*)pqkv;
    dim3 agrid(S_ / 128, B_ * H_);          // (16, 64)
    attn_mma<<<agrid, 128, ATT_SMEM>>>(Qb, Qb + QKVOFF, Qb + 2 * QKVOFF,
                                       (float*)po);

    // O-proj: one tile per block, 512 blocks linear
    gemm_mma<1><<<512, 128, GSMEM1>>>((const float*)po, (const float*)pwo,
                                      bO, out);
}

// round 16
// speedup vs baseline: 1.0228x; 1.0228x over previous
#include <cuda_runtime.h>
#include <math.h>
#include <stdint.h>

#define B_   4
#define S_   2048
#define H_   16
#define DH   64
#define DM   1024
#define MTOT (B_*S_)   // 8192
#define QKVOFF ((size_t)B_*H_*S_*DH)
#define QSCALE 0.180336880111120419f   // 0.125 * log2(e)

// perm3: within each 8-group, logical index c stored at position (c&3)*2+(c>>2)
#define PERM3(c) ((((c) & 3) << 1) | ((c) >> 2))

// -------------------------- device scratch (no allocs) ---------------------
// Q: [B][H][S][DH] prescaled; K: [B][H][S][DH] d-permuted;
// V: [B][H][DH][S] transposed, keys permuted within 8-groups.
__device__ float g_qkv[3 * QKVOFF];
__device__ float g_o[(size_t)B_*S_*DM];      // tf32 attention out
__device__ float g_xt[(size_t)MTOT*DM];      // tf32 x, k-columns permuted
__device__ float g_wqkv[3 * DM * DM];        // tf32 WQ|WK|WV
__device__ float g_wot[DM * DM];             // tf32 WO
__device__ float g_bias[3 * DM];             // bQ|bK|bV

// -------------------------- PTX helpers ------------------------------------
__device__ __forceinline__ uint32_t f2tf(float x) {
    uint32_t r;
    asm("cvt.rna.tf32.f32 %0, %1;" : "=r"(r) : "f"(x));
    return r;
}
__device__ __forceinline__ float ex2(float x) {
    float r;
    asm("ex2.approx.f32 %0, %1;" : "=f"(r) : "f"(x));
    return r;
}
__device__ __forceinline__ void mma_tf32(float c[4], const uint32_t a[4],
                                         const uint32_t b[2]) {
    asm volatile(
        "mma.sync.aligned.m16n8k8.row.col.f32.tf32.tf32.f32 "
        "{%0,%1,%2,%3}, {%4,%5,%6,%7}, {%8,%9}, {%0,%1,%2,%3};"
        : "+f"(c[0]), "+f"(c[1]), "+f"(c[2]), "+f"(c[3])
        : "r"(a[0]), "r"(a[1]), "r"(a[2]), "r"(a[3]), "r"(b[0]), "r"(b[1]));
}
__device__ __forceinline__ uint32_t smem_u32(const void* p) {
    uint32_t a;
    asm("{ .reg .u64 t; cvta.to.shared.u64 t, %1; cvt.u32.u64 %0, t; }"
        : "=r"(a) : "l"(p));
    return a;
}
__device__ __forceinline__ void cp16(uint32_t dst, const void* src) {
    asm volatile("cp.async.cg.shared.global [%0], [%1], 16;"
                 :: "r"(dst), "l"(src));
}
#define CP_COMMIT() asm volatile("cp.async.commit_group;" ::: "memory")
#define CP_WAIT0()  asm volatile("cp.async.wait_group 0;" ::: "memory")

// ---------------- tf32 pre-round: x (k-columns permuted) --------------------
__global__ void preround_x(const float* __restrict__ in, float* __restrict__ out,
                           int n4)
{
    int i = blockIdx.x * blockDim.x + threadIdx.x;
    if (i < n4) {
        float4 v = ((const float4*)in)[i];
        int idx  = i * 4;
        int base = idx & ~7;
        int off  = (idx & 4) ? 1 : 0;
        out[base + off + 0] = __uint_as_float(f2tf(v.x));
        out[base + off + 2] = __uint_as_float(f2tf(v.y));
        out[base + off + 4] = __uint_as_float(f2tf(v.z));
        out[base + off + 6] = __uint_as_float(f2tf(v.w));
    }
}

__global__ void preround_w(const float* __restrict__ WQ, const float* __restrict__ WK,
                           const float* __restrict__ WV, const float* __restrict__ WO,
                           float* __restrict__ wqkv, float* __restrict__ wo)
{
    const int z = blockIdx.y;
    const float* in = (z == 0) ? WQ : (z == 1) ? WK : (z == 2) ? WV : WO;
    float* out = (z < 3) ? wqkv + (size_t)z * DM * DM : wo;
    int i = blockIdx.x * blockDim.x + threadIdx.x;
    float4 v = ((const float4*)in)[i];
    float4 o;
    o.x = __uint_as_float(f2tf(v.x)); o.y = __uint_as_float(f2tf(v.y));
    o.z = __uint_as_float(f2tf(v.z)); o.w = __uint_as_float(f2tf(v.w));
    ((float4*)out)[i] = o;
}

// ---------------------------------------------------------------------------
// Tensor-core tf32 GEMM (R15 structure).
// WMODE 0: fused QKV, persistent; Q prescaled; K d-permuted; V transposed
//          [B][H][DH][S] with key-permutation.
// WMODE 1: O-proj, one tile per block.
// ---------------------------------------------------------------------------
#define PAD_W 136
#define WSZ (32 * PAD_W)
#define NKT (DM / 32)

template<int WMODE>
__device__ __forceinline__ void stage_async(
    const float* __restrict__ A, const float* __restrict__ W,
    uint32_t as, uint32_t ws, int m0, int n0, int k0, int tid, int pad_a)
{
#pragma unroll
    for (int i = 0; i < 8; i++) {
        int idx = tid + i * 128;
        int r   = idx >> 3;
        int c4  = (idx & 7) << 2;
        cp16(as + (r * pad_a + c4) * 4, A + (size_t)(m0 + r) * DM + k0 + c4);
    }
#pragma unroll
    for (int i = 0; i < 8; i++) {
        int idx = tid + i * 128;
        int r   = idx >> 5;
        int c4  = (idx & 31) << 2;
        const float* wp;
        if (WMODE == 0) {
            int n = n0 + c4;
            int sel = n >> 10, nn = n & 1023;
            int h = nn >> 6, e = nn & 63;
            wp = W + (size_t)sel * DM * DM + ((size_t)h * DM + (k0 + r)) * 64 + e;
        } else {
            wp = W + (size_t)(k0 + r) * DM + n0 + c4;
        }
        cp16(ws + (r * PAD_W + c4) * 4, wp);
    }
}

template<int WMODE>
__global__ void __launch_bounds__(128, 2)
gemm_mma(const float* __restrict__ A, const float* __restrict__ W,
         const float* __restrict__ bias, float* __restrict__ out)
{
    constexpr int PA  = (WMODE == 0) ? 40 : 36;
    constexpr int ASZ = 128 * PA;
    constexpr int NTW = (WMODE == 0) ? 24 : 8;
    constexpr int TOT = (WMODE == 0) ? 1536 : 512;

    extern __shared__ float sm[];
    float* As = sm;
    float* Ws = sm + 2 * ASZ;
    const uint32_t asu = smem_u32(As);
    const uint32_t wsu = smem_u32(Ws);

    const int tid  = threadIdx.x;
    const int lane = tid & 31;
    const int wid  = tid >> 5;
    const int mw   = (wid & 1) * 64;
    const int nw   = (wid >> 1) * 64;
    const int gr   = lane >> 2;
    const int gc   = lane & 3;

    int t  = blockIdx.x;
    int m0 = (t / NTW) * 128;
    int n0 = (t % NTW) * 128;

    stage_async<WMODE>(A, W, asu, wsu, m0, n0, 0, tid, PA);
    CP_COMMIT();

    while (true) {
        const int  tn       = t + gridDim.x;
        const bool has_next = (WMODE == 0) && (tn < TOT);
        const int  nm0      = has_next ? (tn / NTW) * 128 : 0;
        const int  nn0      = has_next ? (tn % NTW) * 128 : 0;

        float c[4][8][4];
#pragma unroll
        for (int mt = 0; mt < 4; mt++)
#pragma unroll
            for (int nt = 0; nt < 8; nt++)
#pragma unroll
                for (int j = 0; j < 4; j++) c[mt][nt][j] = 0.f;

        for (int i = 0; i < NKT; i++) {
            const int p = i & 1;
            CP_WAIT0();
            __syncthreads();
            if (i + 1 < NKT) {
                stage_async<WMODE>(A, W, asu + ((p ^ 1) * ASZ) * 4,
                                   wsu + ((p ^ 1) * WSZ) * 4,
                                   m0, n0, (i + 1) * 32, tid, PA);
                CP_COMMIT();
            } else if (has_next) {
                stage_async<WMODE>(A, W, asu + ((p ^ 1) * ASZ) * 4,
                                   wsu + ((p ^ 1) * WSZ) * 4,
                                   nm0, nn0, 0, tid, PA);
                CP_COMMIT();
            }

            const float* as = As + p * ASZ + mw * PA;
            const float* ws = Ws + p * WSZ + nw;
#pragma unroll
            for (int ks = 0; ks < 32; ks += 8) {
                uint32_t af[4][4];
#pragma unroll
                for (int mt = 0; mt < 4; mt++) {
                    if (WMODE == 0) {
                        const float* ap = as + (mt * 16 + gr) * PA + ks + 2 * gc;
                        float2 a0 = *(const float2*)ap;
                        float2 a1 = *(const float2*)(ap + 8 * PA);
                        af[mt][0] = __float_as_uint(a0.x);
                        af[mt][2] = __float_as_uint(a0.y);
                        af[mt][1] = __float_as_uint(a1.x);
                        af[mt][3] = __float_as_uint(a1.y);
                    } else {
                        const float* ap = as + (mt * 16 + gr) * PA + ks + gc;
                        af[mt][0] = __float_as_uint(ap[0]);
                        af[mt][1] = __float_as_uint(ap[8 * PA]);
                        af[mt][2] = __float_as_uint(ap[4]);
                        af[mt][3] = __float_as_uint(ap[8 * PA + 4]);
                    }
                }
                uint32_t bf[8][2];
#pragma unroll
                for (int nt = 0; nt < 8; nt++) {
                    const float* bp = ws + (ks + gc) * PAD_W + nt * 8 + gr;
                    bf[nt][0] = __float_as_uint(bp[0]);
                    bf[nt][1] = __float_as_uint(bp[4 * PAD_W]);
                }
#pragma unroll
                for (int mt = 0; mt < 4; mt++)
#pragma unroll
                    for (int nt = 0; nt < 8; nt++)
                        mma_tf32(c[mt][nt], af[mt], bf[nt]);
            }
        }

        // ---- epilogue for tile (m0, n0) ----
        const int sel   = (WMODE == 0) ? (n0 >> 10) : 0;
        const float scl = (WMODE == 0 && sel == 0) ? QSCALE : 1.0f;
        float* outb = (WMODE == 0) ? out + (size_t)sel * QKVOFF : out;

#pragma unroll
        for (int mt = 0; mt < 4; mt++) {
#pragma unroll
            for (int half = 0; half < 2; half++) {
                int m = m0 + mw + mt * 16 + gr + half * 8;
                int bb = m >> 11, ss = m & (S_ - 1);
                int ssp = (ss & ~7) | PERM3(ss & 7);   // key-permuted (for V)
#pragma unroll
                for (int nt = 0; nt < 8; nt++) {
                    int n = n0 + nw + nt * 8 + 2 * gc;
                    float2 val;
                    val.x = c[mt][nt][half * 2 + 0] + bias[n];
                    val.y = c[mt][nt][half * 2 + 1] + bias[n + 1];
                    if (WMODE == 0) {
                        val.x = __uint_as_float(f2tf(val.x * scl));
                        val.y = __uint_as_float(f2tf(val.y * scl));
                        int nn = n & 1023;
                        int h = nn >> 6, e = nn & 63;
                        if (sel == 2) {
                            // V transposed: [bh][d][key], keys perm3'd
                            float* vb = outb + ((size_t)(bb * H_ + h) * DH + e) * S_;
                            vb[ssp]      = val.x;
                            vb[ssp + S_] = val.y;
                        } else {
                            float* ob = outb + (((size_t)bb * H_ + h) * S_ + ss) * DH;
                            if (sel == 1) {
                                int e0 = (e & ~7) | PERM3(e & 7);
                                int e1 = (e & ~7) | PERM3((e + 1) & 7);
                                ob[e0] = val.x;
                                ob[e1] = val.y;
                            } else {
                                *(float2*)(ob + e) = val;
                            }
                        }
                    } else {
                        *(float2*)(outb + (size_t)m * DM + n) = val;
                    }
                }
            }
        }

        if (!has_next) break;
        t = tn; m0 = nm0; n0 = nn0;
    }
}

#define GSMEM0 (2 * (128 * 40 + WSZ) * 4)   // 75776
#define GSMEM1 (2 * (128 * 36 + WSZ) * 4)   // 71680

// ---------------------------------------------------------------------------
// Tensor-core tf32 flash attention: K d-permuted AND V transposed/key-permuted
// -> both S and PV B-fragments are single LDS.64, conflict-free at stride 72.
// ---------------------------------------------------------------------------
#define AST 68
#define KST 72
#define VST 72
#define KSZ (64 * KST)
#define VSZ (64 * VST)
#define ATT_SMEM ((128*AST + 2*KSZ + 2*VSZ) * 4)   // 108544

__global__ void __launch_bounds__(128, 2)
attn_mma(const float* __restrict__ Q, const float* __restrict__ K,
         const float* __restrict__ V, float* __restrict__ O)
{
    extern __shared__ float sm[];
    float* Pt = sm;
    float* Ks = sm + 128 * AST;      // [2][64][KST]
    float* Vs = Ks + 2 * KSZ;        // [2][64 d][VST keys]
    const uint32_t ksu = smem_u32(Ks);
    const uint32_t vsu = smem_u32(Vs);

    const int tid  = threadIdx.x;
    const int lane = tid & 31;
    const int wid  = tid >> 5;
    const int mw   = wid * 32;
    const int gr   = lane >> 2;
    const int gc   = lane & 3;
    const int bh   = blockIdx.y;
    const int q0   = blockIdx.x * 128;

    const float* Qp = Q + ((size_t)bh * S_ + q0) * DH;
    const float* Kp = K + (size_t)bh * S_ * DH;
    const float* Vp = V + (size_t)bh * DH * S_;    // transposed [d][key]

    // prefetch K/V tile 0 (V rows are d, columns keys)
#pragma unroll
    for (int i = 0; i < 8; i++) {
        int idx = tid + i * 128;
        int r   = idx >> 4;
        int c4  = (idx & 15) << 2;
        cp16(ksu + (r * KST + c4) * 4, Kp + (size_t)r * DH + c4);
        cp16(vsu + (r * VST + c4) * 4, Vp + (size_t)r * S_ + c4);
    }
    CP_COMMIT();

    uint32_t aq[2][8][4];
#pragma unroll
    for (int mt = 0; mt < 2; mt++) {
        const float* qr0 = Qp + (mw + mt * 16 + gr) * DH;
#pragma unroll
        for (int ks = 0; ks < 8; ks++) {
            aq[mt][ks][0] = __float_as_uint(qr0[ks * 8 + gc]);
            aq[mt][ks][1] = __float_as_uint(qr0[8 * DH + ks * 8 + gc]);
            aq[mt][ks][2] = __float_as_uint(qr0[ks * 8 + gc + 4]);
            aq[mt][ks][3] = __float_as_uint(qr0[8 * DH + ks * 8 + gc + 4]);
        }
    }

    float lpart[2][2] = {{0.f, 0.f}, {0.f, 0.f}};
    float co[2][8][4];
#pragma unroll
    for (int mt = 0; mt < 2; mt++)
#pragma unroll
        for (int nt = 0; nt < 8; nt++)
#pragma unroll
            for (int j = 0; j < 4; j++) co[mt][nt][j] = 0.f;

    const int NT = S_ / 64;
    for (int it = 0; it < NT; it++) {
        const int p = it & 1;
        CP_WAIT0();
        __syncthreads();
        if (it + 1 < NT) {
            const int kt1 = (it + 1) * 64;
#pragma unroll
            for (int i = 0; i < 8; i++) {
                int idx = tid + i * 128;
                int r   = idx >> 4;
                int c4  = (idx & 15) << 2;
                cp16(ksu + ((p ^ 1) * KSZ + r * KST + c4) * 4,
                     Kp + (size_t)(kt1 + r) * DH + c4);
                cp16(vsu + ((p ^ 1) * VSZ + r * VST + c4) * 4,
                     Vp + (size_t)r * S_ + kt1 + c4);
            }
            CP_COMMIT();
        }

        const float* ksb = Ks + p * KSZ;
        const float* vsb = Vs + p * VSZ;

        // ---- S = Q @ K^T ----
        float s[2][8][4];
#pragma unroll
        for (int mt = 0; mt < 2; mt++)
#pragma unroll
            for (int nt = 0; nt < 8; nt++)
#pragma unroll
                for (int j = 0; j < 4; j++) s[mt][nt][j] = 0.f;

#pragma unroll
        for (int ks = 0; ks < 8; ks++) {
            uint32_t bk[8][2];
#pragma unroll
            for (int nt = 0; nt < 8; nt++) {
                float2 b2 = *(const float2*)(ksb + (nt * 8 + gr) * KST
                                             + ks * 8 + 2 * gc);
                bk[nt][0] = __float_as_uint(b2.x);
                bk[nt][1] = __float_as_uint(b2.y);
            }
#pragma unroll
            for (int mt = 0; mt < 2; mt++)
#pragma unroll
                for (int nt = 0; nt < 8; nt++)
                    mma_tf32(s[mt][nt], aq[mt][ks], bk[nt]);
        }

        // ---- max-free softmax + P stash ----
#pragma unroll
        for (int mt = 0; mt < 2; mt++) {
#pragma unroll
            for (int hf = 0; hf < 2; hf++) {
                float* pp = Pt + (mw + mt * 16 + gr + 8 * hf) * AST;
                float psum = 0.f;
#pragma unroll
                for (int nt = 0; nt < 8; nt++) {
                    float p0 = ex2(s[mt][nt][hf * 2]);
                    float p1 = ex2(s[mt][nt][hf * 2 + 1]);
                    psum += p0 + p1;
                    float2 pv;
                    pv.x = __uint_as_float(f2tf(p0));
                    pv.y = __uint_as_float(f2tf(p1));
                    *(float2*)(pp + nt * 8 + 2 * gc) = pv;
                }
                lpart[mt][hf] += psum;
            }
        }
        __syncwarp();

        // ---- O += P @ V : V d-major, keys perm3'd -> paired LDS.64 ----
#pragma unroll
        for (int ks = 0; ks < 8; ks++) {
            uint32_t ap[2][4];
#pragma unroll
            for (int mt = 0; mt < 2; mt++) {
                const float* pp = Pt + (mw + mt * 16 + gr) * AST + ks * 8 + gc;
                ap[mt][0] = __float_as_uint(pp[0]);
                ap[mt][1] = __float_as_uint(pp[8 * AST]);
                ap[mt][2] = __float_as_uint(pp[4]);
                ap[mt][3] = __float_as_uint(pp[8 * AST + 4]);
            }
            uint32_t bv[8][2];
#pragma unroll
            for (int nt = 0; nt < 8; nt++) {
                float2 b2 = *(const float2*)(vsb + (nt * 8 + gr) * VST
                                             + ks * 8 + 2 * gc);
                bv[nt][0] = __float_as_uint(b2.x);   // key = ks*8+gc
                bv[nt][1] = __float_as_uint(b2.y);   // key = ks*8+gc+4
            }
#pragma unroll
            for (int mt = 0; mt < 2; mt++)
#pragma unroll
                for (int nt = 0; nt < 8; nt++)
                    mma_tf32(co[mt][nt], ap[mt], bv[nt]);
        }
    }

    // ---- epilogue ----
    const int b = bh >> 4, h = bh & 15;
#pragma unroll
    for (int mt = 0; mt < 2; mt++) {
#pragma unroll
        for (int hf = 0; hf < 2; hf++) {
            float l = lpart[mt][hf];
            l += __shfl_xor_sync(0xffffffffu, l, 1);
            l += __shfl_xor_sync(0xffffffffu, l, 2);
            float inv = 1.f / l;
            int q = q0 + mw + mt * 16 + gr + 8 * hf;
            float* op = O + ((size_t)b * S_ + q) * DM + h * DH;
#pragma unroll
            for (int nt = 0; nt < 8; nt++) {
                float2 val;
                val.x = __uint_as_float(f2tf(co[mt][nt][hf * 2]     * inv));
                val.y = __uint_as_float(f2tf(co[mt][nt][hf * 2 + 1] * inv));
                *(float2*)(op + nt * 8 + 2 * gc) = val;
            }
        }
    }
}

// ---------------------------------------------------------------------------
extern "C" void kernel_launch(void* const* d_in, const int* in_sizes, int n_in,
                              void* d_out, int out_size)
{
    (void)in_sizes; (void)n_in; (void)out_size;
    const float* x  = (const float*)d_in[0];
    const float* WQ = (const float*)d_in[1];
    const float* WK = (const float*)d_in[2];
    const float* WV = (const float*)d_in[3];
    const float* WO = (const float*)d_in[4];
    const float* bQ = (const float*)d_in[5];
    const float* bK = (const float*)d_in[6];
    const float* bV = (const float*)d_in[7];
    const float* bO = (const float*)d_in[8];
    float* out = (float*)d_out;

    void *pqkv, *po, *pxt, *pwqkv, *pwo, *pbias;
    cudaGetSymbolAddress(&pqkv, g_qkv);
    cudaGetSymbolAddress(&po, g_o);
    cudaGetSymbolAddress(&pxt, g_xt);
    cudaGetSymbolAddress(&pwqkv, g_wqkv);
    cudaGetSymbolAddress(&pwo, g_wot);
    cudaGetSymbolAddress(&pbias, g_bias);

    static int attr_set = 0;
    if (!attr_set) {
        cudaFuncSetAttribute(attn_mma, cudaFuncAttributeMaxDynamicSharedMemorySize,
                             ATT_SMEM);
        cudaFuncSetAttribute(gemm_mma<0>, cudaFuncAttributeMaxDynamicSharedMemorySize,
                             GSMEM0);
        cudaFuncSetAttribute(gemm_mma<1>, cudaFuncAttributeMaxDynamicSharedMemorySize,
                             GSMEM1);
        attr_set = 1;
    }

    preround_x<<<(MTOT * DM / 4 + 255) / 256, 256>>>(x, (float*)pxt, MTOT * DM / 4);
    preround_w<<<dim3(DM * DM / 4 / 256, 4), 256>>>(WQ, WK, WV, WO,
                                                    (float*)pwqkv, (float*)pwo);
    cudaMemcpyAsync((float*)pbias,          bQ, DM * 4, cudaMemcpyDeviceToDevice);
    cudaMemcpyAsync((float*)pbias + DM,     bK, DM * 4, cudaMemcpyDeviceToDevice);
    cudaMemcpyAsync((float*)pbias + 2 * DM, bV, DM * 4, cudaMemcpyDeviceToDevice);

    gemm_mma<0><<<304, 128, GSMEM0>>>((const float*)pxt, (const float*)pwqkv,
                                      (const float*)pbias, (float*)pqkv);

    const float* Qb = (const float*)pqkv;
    dim3 agrid(S_ / 128, B_ * H_);          // (16, 64)
    attn_mma<<<agrid, 128, ATT_SMEM>>>(Qb, Qb + QKVOFF, Qb + 2 * QKVOFF,
                                       (float*)po);

    gemm_mma<1><<<512, 128, GSMEM1>>>((const float*)po, (const float*)pwo,
                                      bO, out);
}